// round 16
// baseline (speedup 1.0000x reference)
#include <cuda_runtime.h>
#include <cuda_fp16.h>
#include <cstdint>
#include <math.h>

#define Bsz 2
#define Tt  2048
#define Cc  2048
#define NH  8
#define HD  256
#define HH  128
#define SCALE 0.08838834764831845f   // 1/sqrt(128)

// ---------------- scratch (device globals: sanctioned, no alloc) ----------------
__device__ __half g_V [Bsz*Tt*Cc];     // fp16, written by V GEMM epilogue
__device__ __half g_q1[Bsz*NH*Tt*HH];  // fp16, pre-scaled by SCALE*log2e
__device__ __half g_q2[Bsz*NH*Tt*HH];
__device__ __half g_k1[Bsz*NH*Tt*HH];
__device__ __half g_k2[Bsz*NH*Tt*HH];
__device__ __half g_y [Bsz*Tt*Cc];     // fp16, written by attn epilogue
__device__ __half g_X [Bsz*Tt*Cc];     // fp16-rounded x
__device__ __half g_Wq[Cc*Cc];         // fp16-rounded weights
__device__ __half g_Wk[Cc*Cc];
__device__ __half g_Wv[Cc*Cc];
__device__ __half g_Wo[Cc*Cc];
__device__ float g_lam;

// ---------------- helpers ----------------
__device__ __forceinline__ unsigned h2pack(float a, float b) {
    __half2 h = __floats2half2_rn(a, b);
    return *(unsigned*)&h;
}

__device__ __forceinline__ void mma_f16(float* d, const unsigned* a, const unsigned* b) {
    asm volatile(
        "mma.sync.aligned.m16n8k16.row.col.f32.f16.f16.f32 "
        "{%0,%1,%2,%3}, {%4,%5,%6,%7}, {%8,%9}, {%0,%1,%2,%3};"
        : "+f"(d[0]), "+f"(d[1]), "+f"(d[2]), "+f"(d[3])
        : "r"(a[0]), "r"(a[1]), "r"(a[2]), "r"(a[3]), "r"(b[0]), "r"(b[1]));
}

__device__ __forceinline__ void ldmx2t(unsigned& r0, unsigned& r1, unsigned addr) {
    asm volatile("ldmatrix.sync.aligned.m8n8.x2.trans.shared.b16 {%0,%1}, [%2];"
                 : "=r"(r0), "=r"(r1) : "r"(addr));
}

__device__ __forceinline__ void cp_async16(unsigned dst, const void* src) {
    asm volatile("cp.async.cg.shared.global [%0], [%1], 16;" :: "r"(dst), "l"(src));
}
__device__ __forceinline__ void cp_commit()  { asm volatile("cp.async.commit_group;"); }
__device__ __forceinline__ unsigned smem_u32(const void* p) {
    unsigned r;
    asm("{.reg .u64 t; cvta.to.shared.u64 t, %1; cvt.u32.u64 %0, t;}" : "=r"(r) : "l"(p));
    return r;
}

// ---------------- fp16 pre-rounding pass (+ fused lambda) ----------------
__global__ __launch_bounds__(256)
void cvt_kernel(const float* __restrict__ x,  const float* __restrict__ wq,
                const float* __restrict__ wk, const float* __restrict__ wv,
                const float* __restrict__ wo,
                const float* __restrict__ lq1, const float* __restrict__ lk1,
                const float* __restrict__ lq2, const float* __restrict__ lk2)
{
    const size_t NSEG = (size_t)Cc * Cc;
    int z = blockIdx.z;
    const float* src;
    __half* dst;
    if      (z == 0) { src = x;        dst = g_X; }
    else if (z == 1) { src = x + NSEG; dst = g_X + NSEG; }
    else if (z == 2) { src = wq;       dst = g_Wq; }
    else if (z == 3) { src = wk;       dst = g_Wk; }
    else if (z == 4) { src = wv;       dst = g_Wv; }
    else             { src = wo;       dst = g_Wo; }
    size_t i = ((size_t)blockIdx.x * 256 + threadIdx.x) * 4;
    float4 v = *(const float4*)(src + i);
    uint2 u;
    u.x = h2pack(v.x, v.y);
    u.y = h2pack(v.z, v.w);
    *(uint2*)(dst + i) = u;

    if (z == 5 && blockIdx.x == 0) {
        int d = threadIdx.x;
        float p1 = lq1[d] * lk1[d];
        float p2 = lq2[d] * lk2[d];
#pragma unroll
        for (int o = 16; o; o >>= 1) {
            p1 += __shfl_xor_sync(0xffffffffu, p1, o);
            p2 += __shfl_xor_sync(0xffffffffu, p2, o);
        }
        __shared__ float w1[8], w2[8];
        if ((d & 31) == 0) { w1[d >> 5] = p1; w2[d >> 5] = p2; }
        __syncthreads();
        if (d == 0) {
            float s1 = 0.f, s2 = 0.f;
            for (int i2 = 0; i2 < 8; i2++) { s1 += w1[i2]; s2 += w2[i2]; }
            g_lam = expf(s1) - expf(s2) + 0.2f;
        }
    }
}

// ---------------- FP16 GEMM: 8 warps of 64x32, 256 thr, 2 CTAs/SM ----------------
// C[M,N] = alpha * A[M,K] @ B[N,K]^T, fp16 in, fp32 accum.
// block 128x128x64, RPAD 36 words (64 halves + pad), 3 stages, 1 sync/iter.
// launch_bounds(256,2) caps regs at 128 -> true 16 warps/SM.
// mode: 0 = fp32 store, 1 = fp16 store (V), 2 = fused prep -> q1/q2, 3 = -> k1/k2.
#define RPAD 36
#define STG_W 9216   // words per stage (A 128*36 + B 128*36)
#define GSM   (STG_W * 3 * 4)   // 110592 B

__device__ __forceinline__
void tg_fill(unsigned sstage, const __half* __restrict__ Ap0, const __half* __restrict__ Bp0,
             int K, int k0, int tid)
{
#pragma unroll
    for (int i = 0; i < 4; i++) {
        int seg = tid + 256 * i;              // 0..1023
        int row = seg >> 3, c16 = (seg & 7) << 4;
        cp_async16(sstage + (unsigned)(row * 144 + c16),
                   Ap0 + (size_t)row * K + k0 + (c16 >> 1));
        cp_async16(sstage + (unsigned)(18432 + row * 144 + c16),
                   Bp0 + (size_t)row * K + k0 + (c16 >> 1));
    }
}

__device__ __forceinline__
void tgemm_body(const __half* __restrict__ A, const __half* __restrict__ B,
                float* __restrict__ C, int N, int K, float alpha, int mode)
{
    extern __shared__ float smem[];

    const int tid  = threadIdx.x;
    const int lane = tid & 31;
    const int wid  = tid >> 5;
    const int wm   = (wid & 1) * 64;      // 2 warp-rows
    const int wn   = (wid >> 1) * 32;     // 4 warp-cols
    const int r    = lane >> 2;
    const int c    = lane & 3;
    const int m0   = blockIdx.y * 128;
    const int n0   = blockIdx.x * 128;

    const unsigned sb = smem_u32(smem);
    const __half* Ap0 = A + (size_t)m0 * K;
    const __half* Bp0 = B + (size_t)n0 * K;

    float acc[4][4][4];
#pragma unroll
    for (int i = 0; i < 4; i++)
#pragma unroll
        for (int j = 0; j < 4; j++)
#pragma unroll
            for (int e = 0; e < 4; e++) acc[i][j][e] = 0.f;

    const int nit = K >> 6;               // 32
    tg_fill(sb, Ap0, Bp0, K, 0, tid);
    cp_commit();

    int cur = 0;
    for (int it = 0; it < nit; ++it) {
        if (it + 1 < nit) {
            int nstage = (it + 1) % 3;
            tg_fill(sb + (unsigned)nstage * STG_W * 4, Ap0, Bp0, K, (it + 1) << 6, tid);
        }
        cp_commit();
        asm volatile("cp.async.wait_group 1;");
        __syncthreads();

        const unsigned* As = (const unsigned*)smem + cur * STG_W;
        const unsigned* Bs = As + 4608;
#pragma unroll
        for (int ks = 0; ks < 4; ks++) {           // 4 k16 steps
            unsigned af[4][4], bf[4][2];
#pragma unroll
            for (int mi = 0; mi < 4; mi++) {
                const unsigned* ap = As + (wm + 16 * mi) * RPAD + 8 * ks + c;
                af[mi][0] = ap[r * RPAD];
                af[mi][1] = ap[(r + 8) * RPAD];
                af[mi][2] = ap[r * RPAD + 4];
                af[mi][3] = ap[(r + 8) * RPAD + 4];
            }
#pragma unroll
            for (int nj = 0; nj < 4; nj++) {
                const unsigned* bp = Bs + (wn + 8 * nj) * RPAD + 8 * ks + c;
                bf[nj][0] = bp[r * RPAD];
                bf[nj][1] = bp[r * RPAD + 4];
            }
#pragma unroll
            for (int mi = 0; mi < 4; mi++)
#pragma unroll
                for (int nj = 0; nj < 4; nj++)
                    mma_f16(acc[mi][nj], af[mi], bf[nj]);
        }
        cur = (cur == 2) ? 0 : cur + 1;
    }

    if (mode == 0) {
#pragma unroll
        for (int mi = 0; mi < 4; mi++)
#pragma unroll
            for (int nj = 0; nj < 4; nj++) {
                int row = m0 + wm + 16 * mi + r;
                int col = n0 + wn + 8 * nj + 2 * c;
                *(float2*)(C + (size_t)row * N + col) =
                    make_float2(alpha * acc[mi][nj][0], alpha * acc[mi][nj][1]);
                *(float2*)(C + (size_t)(row + 8) * N + col) =
                    make_float2(alpha * acc[mi][nj][2], alpha * acc[mi][nj][3]);
            }
        return;
    }
    if (mode == 1) {                       // V: fp16 store
#pragma unroll
        for (int mi = 0; mi < 4; mi++)
#pragma unroll
            for (int nj = 0; nj < 4; nj++) {
                int row = m0 + wm + 16 * mi + r;
                int col = n0 + wn + 8 * nj + 2 * c;
                *(unsigned*)(g_V + (size_t)row * N + col)       = h2pack(acc[mi][nj][0], acc[mi][nj][1]);
                *(unsigned*)(g_V + (size_t)(row + 8) * N + col) = h2pack(acc[mi][nj][2], acc[mi][nj][3]);
            }
        return;
    }

    // ---- fused rmsnorm + (head-indexed) rotary epilogue (Q/K GEMMs) ----
    __syncthreads();
    float* tile = smem;                 // 128 x 132 fp32
    float* cs   = smem + 16896;         // cj[64], sj[64]
#pragma unroll
    for (int mi = 0; mi < 4; mi++)
#pragma unroll
        for (int nj = 0; nj < 4; nj++) {
            int rr  = wm + 16 * mi + r;
            int cc2 = wn + 8 * nj + 2 * c;
            tile[rr * 132 + cc2]           = acc[mi][nj][0];
            tile[rr * 132 + cc2 + 1]       = acc[mi][nj][1];
            tile[(rr + 8) * 132 + cc2]     = acc[mi][nj][2];
            tile[(rr + 8) * 132 + cc2 + 1] = acc[mi][nj][3];
        }
    const int h    = n0 >> 8;
    const int half = (n0 >> 7) & 1;
    if (tid < 64) {
        // buggy-rotary angle: position index = head index h
        float ang = (float)h * exp2f(-(float)tid * (13.287712379549449f / 64.0f));
        cs[tid]      = cosf(ang);
        cs[64 + tid] = sinf(ang);
    }
    __syncthreads();

    if (tid < 128) {
        const int row = tid;
        const float* tr = tile + row * 132;
        float ss = 0.f;
#pragma unroll
        for (int i = 0; i < 32; i++) {
            float4 v4 = *(const float4*)(tr + 4 * i);
            ss += v4.x * v4.x + v4.y * v4.y + v4.z * v4.z + v4.w * v4.w;
        }
        const float osc = (mode == 2) ? (SCALE * 1.4426950408889634f) : 1.0f;
        const float rn  = rsqrtf(ss * (1.0f / 128.0f) + 1.1920929e-07f) * osc;

        const int bt = m0 + row;
        const int b  = bt >> 11;
        const int tt = bt & 2047;
        __half* dst = (mode == 2) ? (half ? g_q2 : g_q1) : (half ? g_k2 : g_k1);
        dst += ((size_t)(b * NH + h) * Tt + tt) * HH;

#pragma unroll
        for (int jb = 0; jb < 16; jb++) {
            float4 v4 = *(const float4*)(tr + 4 * jb);
            float4 p4 = *(const float4*)(tr + 64 + 4 * jb);
            float c0 = cs[4 * jb + 0], c1 = cs[4 * jb + 1];
            float c2 = cs[4 * jb + 2], c3 = cs[4 * jb + 3];
            float s0 = cs[64 + 4 * jb + 0], s1 = cs[64 + 4 * jb + 1];
            float s2 = cs[64 + 4 * jb + 2], s3 = cs[64 + 4 * jb + 3];
            uint2 lo, hi;
            lo.x = h2pack(rn * (v4.x * c0 + p4.x * s0), rn * (v4.y * c1 + p4.y * s1));
            lo.y = h2pack(rn * (v4.z * c2 + p4.z * s2), rn * (v4.w * c3 + p4.w * s3));
            hi.x = h2pack(rn * (p4.x * c0 - v4.x * s0), rn * (p4.y * c1 - v4.y * s1));
            hi.y = h2pack(rn * (p4.z * c2 - v4.z * s2), rn * (p4.w * c3 - v4.w * s3));
            *(uint2*)(dst + 4 * jb)      = lo;
            *(uint2*)(dst + 64 + 4 * jb) = hi;
        }
    }
}

__global__ __launch_bounds__(256, 2)
void tgemm_qkv()
{
    const __half* B = (blockIdx.z == 0) ? g_Wq : (blockIdx.z == 1) ? g_Wk : g_Wv;
    int mode = (blockIdx.z == 0) ? 2 : (blockIdx.z == 1) ? 3 : 1;
    tgemm_body(g_X, B, (float*)0, Cc, Cc, 1.0f, mode);
}

__global__ __launch_bounds__(256, 2)
void tgemm_wo(float* __restrict__ out)
{
    tgemm_body(g_y, g_Wo, out, Cc, Cc, 0.8f, 0);
}

// ---------------- fp16 tensor-core dual causal flash attention ----------------
// (frozen R15 winner) grid (16 bh, 32 qtiles reversed), 256 thr = 8 warps.
// 64-key tiles, double-buffered cp.async; V via ldmatrix.trans.
__global__ __launch_bounds__(256, 1)
void attn_tc()
{
    extern __shared__ float smf[];
    unsigned* q_s = (unsigned*)smf;        // 8704 w
    unsigned* k_s = q_s + 8704;            // 17408 w
    // v region at word 26112, size 16896 w

    const int tid   = threadIdx.x;
    const int lane  = tid & 31;
    const int w     = tid >> 5;
    const int g     = lane >> 2;
    const int t     = lane & 3;
    const int br    = w & 1;
    const int strip = w >> 1;
    const int mrow  = strip * 16;
    const int bh    = blockIdx.x;
    const int qt    = (int)gridDim.y - 1 - (int)blockIdx.y;  // big tiles first
    const int q0    = qt * 64;
    const int ntiles = qt + 1;

    const unsigned qsb = smem_u32(smf);
    const unsigned ksb = qsb + 8704u * 4;
    const unsigned vsb = qsb + 26112u * 4;

    const int b_ = bh >> 3, h_ = bh & 7;
    const __half* q1b = g_q1 + (size_t)bh * Tt * HH;
    const __half* q2b = g_q2 + (size_t)bh * Tt * HH;
    const __half* k1b = g_k1 + (size_t)bh * Tt * HH;
    const __half* k2b = g_k2 + (size_t)bh * Tt * HH;
    const __half* vsrc = g_V + (size_t)(b_ * Tt) * Cc + h_ * HD;

    // Q tile
    for (int i = tid; i < 2048; i += 256) {
        int bq = i >> 10;
        int r  = (i >> 4) & 63;
        int c16 = (i & 15) << 4;
        cp_async16(qsb + (unsigned)((bq * 4352 + r * 68) * 4 + c16),
                   q1b + (bq ? (q2b - q1b) : 0) + (size_t)(q0 + r) * HH + (c16 >> 1));
    }
    // K/V tile 0 into buffer 0
    for (int i = tid; i < 2048; i += 256) {
        int bq = i >> 10;
        int r  = (i >> 4) & 63;
        int c16 = (i & 15) << 4;
        cp_async16(ksb + (unsigned)((bq * 4352 + r * 68) * 4 + c16),
                   k1b + (bq ? (k2b - k1b) : 0) + (size_t)r * HH + (c16 >> 1));
    }
    for (int i = tid; i < 2048; i += 256) {
        int r  = i >> 5;
        int c16 = (i & 31) << 4;
        cp_async16(vsb + (unsigned)(r * 132 * 4 + c16), vsrc + (size_t)r * Cc + (c16 >> 1));
    }
    cp_commit();

    float oa[32][4];
#pragma unroll
    for (int i = 0; i < 32; i++) { oa[i][0]=0.f; oa[i][1]=0.f; oa[i][2]=0.f; oa[i][3]=0.f; }
    float m0 = -1e30f, m1 = -1e30f, l0 = 0.f, l1 = 0.f;

    for (int kb = 0; kb < ntiles; kb++) {
        const int buf = kb & 1;
        if (kb + 1 < ntiles) {
            const int kr = (kb + 1) * 64;
            const unsigned ko = (unsigned)((buf ^ 1) * 8704) * 4;
            const unsigned vo = (unsigned)((buf ^ 1) * 8448) * 4;
            for (int i = tid; i < 2048; i += 256) {
                int bq = i >> 10;
                int r  = (i >> 4) & 63;
                int c16 = (i & 15) << 4;
                cp_async16(ksb + ko + (unsigned)((bq * 4352 + r * 68) * 4 + c16),
                           k1b + (bq ? (k2b - k1b) : 0) + (size_t)(kr + r) * HH + (c16 >> 1));
            }
            for (int i = tid; i < 2048; i += 256) {
                int r  = i >> 5;
                int c16 = (i & 31) << 4;
                cp_async16(vsb + vo + (unsigned)(r * 132 * 4 + c16),
                           vsrc + (size_t)(kr + r) * Cc + (c16 >> 1));
            }
        }
        cp_commit();
        asm volatile("cp.async.wait_group 1;");
        __syncthreads();

        // ---- S = Q K^T (16 rows x 64 keys, own branch), 8 k16 steps ----
        float sc[8][4];
#pragma unroll
        for (int nt = 0; nt < 8; nt++) { sc[nt][0]=0.f; sc[nt][1]=0.f; sc[nt][2]=0.f; sc[nt][3]=0.f; }
        {
            const unsigned* qb = q_s + br * 4352 + mrow * 68;
            const unsigned* kk = k_s + buf * 8704 + br * 4352;
#pragma unroll
            for (int ks = 0; ks < 8; ks++) {
                int col = 8 * ks + t;
                unsigned a[4];
                a[0] = qb[g * 68 + col];
                a[1] = qb[(g + 8) * 68 + col];
                a[2] = qb[g * 68 + col + 4];
                a[3] = qb[(g + 8) * 68 + col + 4];
#pragma unroll
                for (int nt = 0; nt < 8; nt++) {
                    unsigned bb[2];
                    bb[0] = kk[(8 * nt + g) * 68 + col];
                    bb[1] = kk[(8 * nt + g) * 68 + col + 4];
                    mma_f16(sc[nt], a, bb);
                }
            }
        }

        // ---- causal mask (diagonal tile only) ----
        if (kb == qt) {
            int row0 = q0 + mrow + g;
            int row1 = row0 + 8;
#pragma unroll
            for (int nt = 0; nt < 8; nt++) {
                int kc = kb * 64 + 8 * nt + 2 * t;
                if (kc     > row0) sc[nt][0] = -1e30f;
                if (kc + 1 > row0) sc[nt][1] = -1e30f;
                if (kc     > row1) sc[nt][2] = -1e30f;
                if (kc + 1 > row1) sc[nt][3] = -1e30f;
            }
        }

        // ---- online softmax (base-2 domain), warp-local ----
        float mx0 = -1e30f, mx1 = -1e30f;
#pragma unroll
        for (int nt = 0; nt < 8; nt++) {
            mx0 = fmaxf(mx0, fmaxf(sc[nt][0], sc[nt][1]));
            mx1 = fmaxf(mx1, fmaxf(sc[nt][2], sc[nt][3]));
        }
        mx0 = fmaxf(mx0, __shfl_xor_sync(0xffffffffu, mx0, 1));
        mx0 = fmaxf(mx0, __shfl_xor_sync(0xffffffffu, mx0, 2));
        mx1 = fmaxf(mx1, __shfl_xor_sync(0xffffffffu, mx1, 1));
        mx1 = fmaxf(mx1, __shfl_xor_sync(0xffffffffu, mx1, 2));
        float nm0 = fmaxf(m0, mx0), nm1 = fmaxf(m1, mx1);
        float c0 = exp2f(m0 - nm0), c1 = exp2f(m1 - nm1);
        m0 = nm0; m1 = nm1;
        float s0 = 0.f, s1 = 0.f;
#pragma unroll
        for (int nt = 0; nt < 8; nt++) {
            sc[nt][0] = exp2f(sc[nt][0] - m0);
            sc[nt][1] = exp2f(sc[nt][1] - m0);
            sc[nt][2] = exp2f(sc[nt][2] - m1);
            sc[nt][3] = exp2f(sc[nt][3] - m1);
            s0 += sc[nt][0] + sc[nt][1];
            s1 += sc[nt][2] + sc[nt][3];
        }
        s0 += __shfl_xor_sync(0xffffffffu, s0, 1);
        s0 += __shfl_xor_sync(0xffffffffu, s0, 2);
        s1 += __shfl_xor_sync(0xffffffffu, s1, 1);
        s1 += __shfl_xor_sync(0xffffffffu, s1, 2);
        l0 = l0 * c0 + s0;
        l1 = l1 * c1 + s1;
        if (c0 != 1.f || c1 != 1.f) {
#pragma unroll
            for (int nt = 0; nt < 32; nt++) {
                oa[nt][0] *= c0; oa[nt][1] *= c0;
                oa[nt][2] *= c1; oa[nt][3] *= c1;
            }
        }

        // ---- O += P V : P packs straight from C-frags; V via ldmatrix.trans ----
#pragma unroll
        for (int kp = 0; kp < 4; kp++) {           // four k16 steps over 64 keys
            unsigned pa[4];
            pa[0] = h2pack(sc[2 * kp][0],     sc[2 * kp][1]);
            pa[1] = h2pack(sc[2 * kp][2],     sc[2 * kp][3]);
            pa[2] = h2pack(sc[2 * kp + 1][0], sc[2 * kp + 1][1]);
            pa[3] = h2pack(sc[2 * kp + 1][2], sc[2 * kp + 1][3]);
            unsigned vrow = vsb + (unsigned)(buf * 8448 + (16 * kp + (lane & 15)) * 132) * 4;
#pragma unroll
            for (int nt = 0; nt < 32; nt++) {
                unsigned vb[2];
                ldmx2t(vb[0], vb[1], vrow + nt * 16);
                mma_f16(oa[nt], pa, vb);
            }
        }
        __syncthreads();
    }

    // ---- combine branches: y = O1/l1 - lam * O2/l2 -> fp16 ----
    float* ex = smf;                       // reuse Q/K region
    float lam = g_lam;
    if (br == 0) {
        float r0 = 1.f / l0, r1 = 1.f / l1;
        float* eb = ex + strip * 4096;
#pragma unroll
        for (int nt = 0; nt < 32; nt++) {
            eb[(nt * 4 + 0) * 32 + lane] = oa[nt][0] * r0;
            eb[(nt * 4 + 1) * 32 + lane] = oa[nt][1] * r0;
            eb[(nt * 4 + 2) * 32 + lane] = oa[nt][2] * r1;
            eb[(nt * 4 + 3) * 32 + lane] = oa[nt][3] * r1;
        }
    }
    __syncthreads();
    if (br == 1) {
        float r0 = lam / l0, r1 = lam / l1;
        const float* eb = ex + strip * 4096;
        int row0 = q0 + mrow + g;
        __half* y0p = g_y + ((size_t)(b_ * Tt) + row0) * Cc + h_ * HD;
        __half* y1p = y0p + (size_t)8 * Cc;
#pragma unroll
        for (int nt = 0; nt < 32; nt++) {
            int col = 8 * nt + 2 * t;
            *(unsigned*)(y0p + col) = h2pack(eb[(nt * 4 + 0) * 32 + lane] - oa[nt][0] * r0,
                                             eb[(nt * 4 + 1) * 32 + lane] - oa[nt][1] * r0);
            *(unsigned*)(y1p + col) = h2pack(eb[(nt * 4 + 2) * 32 + lane] - oa[nt][2] * r1,
                                             eb[(nt * 4 + 3) * 32 + lane] - oa[nt][3] * r1);
        }
    }
}

// ---------------- launcher ----------------
extern "C" void kernel_launch(void* const* d_in, const int* in_sizes, int n_in,
                              void* d_out, int out_size)
{
    const float* x   = (const float*)d_in[0];
    const float* wq  = (const float*)d_in[1];
    const float* wk  = (const float*)d_in[2];
    const float* wv  = (const float*)d_in[3];
    const float* wo  = (const float*)d_in[4];
    const float* lq1 = (const float*)d_in[5];
    const float* lk1 = (const float*)d_in[6];
    const float* lq2 = (const float*)d_in[7];
    const float* lk2 = (const float*)d_in[8];
    float* out = (float*)d_out;

    cudaFuncSetAttribute(tgemm_qkv, cudaFuncAttributeMaxDynamicSharedMemorySize, GSM);
    cudaFuncSetAttribute(tgemm_wo,  cudaFuncAttributeMaxDynamicSharedMemorySize, GSM);

    cvt_kernel<<<dim3(4096, 1, 6), 256>>>(x, wq, wk, wv, wo, lq1, lk1, lq2, lk2);
    tgemm_qkv<<<dim3(Cc / 128, (Bsz * Tt) / 128, 3), 256, GSM>>>();

    int smem = 43008 * 4;   // 172032 B
    cudaFuncSetAttribute(attn_tc, cudaFuncAttributeMaxDynamicSharedMemorySize, smem);
    attn_tc<<<dim3(Bsz * NH, Tt / 64), 256, smem>>>();

    tgemm_wo<<<dim3(Cc / 128, (Bsz * Tt) / 128), 256, GSM>>>(out);
}

// round 17
// speedup vs baseline: 1.0189x; 1.0189x over previous
#include <cuda_runtime.h>
#include <cuda_fp16.h>
#include <cstdint>
#include <math.h>

#define Bsz 2
#define Tt  2048
#define Cc  2048
#define NH  8
#define HD  256
#define HH  128
#define SCALE 0.08838834764831845f   // 1/sqrt(128)

// ---------------- scratch (device globals: sanctioned, no alloc) ----------------
__device__ __half g_V [Bsz*Tt*Cc];     // fp16, written by V GEMM epilogue
__device__ __half g_q1[Bsz*NH*Tt*HH];  // fp16, pre-scaled by SCALE*log2e
__device__ __half g_q2[Bsz*NH*Tt*HH];
__device__ __half g_k1[Bsz*NH*Tt*HH];
__device__ __half g_k2[Bsz*NH*Tt*HH];
__device__ __half g_y [Bsz*Tt*Cc];     // fp16, written by attn epilogue
__device__ __half g_X [Bsz*Tt*Cc];     // fp16-rounded x
__device__ __half g_Wq[Cc*Cc];         // fp16-rounded weights
__device__ __half g_Wk[Cc*Cc];
__device__ __half g_Wv[Cc*Cc];
__device__ __half g_Wo[Cc*Cc];
__device__ float g_lam;

// ---------------- helpers ----------------
__device__ __forceinline__ unsigned h2pack(float a, float b) {
    __half2 h = __floats2half2_rn(a, b);
    return *(unsigned*)&h;
}

__device__ __forceinline__ void mma_f16(float* d, const unsigned* a, const unsigned* b) {
    asm volatile(
        "mma.sync.aligned.m16n8k16.row.col.f32.f16.f16.f32 "
        "{%0,%1,%2,%3}, {%4,%5,%6,%7}, {%8,%9}, {%0,%1,%2,%3};"
        : "+f"(d[0]), "+f"(d[1]), "+f"(d[2]), "+f"(d[3])
        : "r"(a[0]), "r"(a[1]), "r"(a[2]), "r"(a[3]), "r"(b[0]), "r"(b[1]));
}

__device__ __forceinline__ void ldmx2t(unsigned& r0, unsigned& r1, unsigned addr) {
    asm volatile("ldmatrix.sync.aligned.m8n8.x2.trans.shared.b16 {%0,%1}, [%2];"
                 : "=r"(r0), "=r"(r1) : "r"(addr));
}

__device__ __forceinline__ void cp_async16(unsigned dst, const void* src) {
    asm volatile("cp.async.cg.shared.global [%0], [%1], 16;" :: "r"(dst), "l"(src));
}
__device__ __forceinline__ void cp_commit()  { asm volatile("cp.async.commit_group;"); }
__device__ __forceinline__ unsigned smem_u32(const void* p) {
    unsigned r;
    asm("{.reg .u64 t; cvta.to.shared.u64 t, %1; cvt.u32.u64 %0, t;}" : "=r"(r) : "l"(p));
    return r;
}

// ---------------- fp16 pre-rounding pass (+ fused lambda) ----------------
__global__ __launch_bounds__(256)
void cvt_kernel(const float* __restrict__ x,  const float* __restrict__ wq,
                const float* __restrict__ wk, const float* __restrict__ wv,
                const float* __restrict__ wo,
                const float* __restrict__ lq1, const float* __restrict__ lk1,
                const float* __restrict__ lq2, const float* __restrict__ lk2)
{
    const size_t NSEG = (size_t)Cc * Cc;
    int z = blockIdx.z;
    const float* src;
    __half* dst;
    if      (z == 0) { src = x;        dst = g_X; }
    else if (z == 1) { src = x + NSEG; dst = g_X + NSEG; }
    else if (z == 2) { src = wq;       dst = g_Wq; }
    else if (z == 3) { src = wk;       dst = g_Wk; }
    else if (z == 4) { src = wv;       dst = g_Wv; }
    else             { src = wo;       dst = g_Wo; }
    size_t i = ((size_t)blockIdx.x * 256 + threadIdx.x) * 4;
    float4 v = *(const float4*)(src + i);
    uint2 u;
    u.x = h2pack(v.x, v.y);
    u.y = h2pack(v.z, v.w);
    *(uint2*)(dst + i) = u;

    if (z == 5 && blockIdx.x == 0) {
        int d = threadIdx.x;
        float p1 = lq1[d] * lk1[d];
        float p2 = lq2[d] * lk2[d];
#pragma unroll
        for (int o = 16; o; o >>= 1) {
            p1 += __shfl_xor_sync(0xffffffffu, p1, o);
            p2 += __shfl_xor_sync(0xffffffffu, p2, o);
        }
        __shared__ float w1[8], w2[8];
        if ((d & 31) == 0) { w1[d >> 5] = p1; w2[d >> 5] = p2; }
        __syncthreads();
        if (d == 0) {
            float s1 = 0.f, s2 = 0.f;
            for (int i2 = 0; i2 < 8; i2++) { s1 += w1[i2]; s2 += w2[i2]; }
            g_lam = expf(s1) - expf(s2) + 0.2f;
        }
    }
}

// ---------------- FP16 GEMM, cp.async, 4 warps of 64x64, k-tile 64 ----------------
// (frozen R14/R15 winner — 128 threads, ~110 us/GEMM, at fallback-HMMA roofline)
#define RPAD 36
#define STG_W 9216   // words per stage (A 128*36 + B 128*36)
#define GSM   (STG_W * 3 * 4)   // 110592 B

__device__ __forceinline__
void tg_fill(unsigned sstage, const __half* __restrict__ Ap0, const __half* __restrict__ Bp0,
             int K, int k0, int tid)
{
#pragma unroll
    for (int i = 0; i < 8; i++) {
        int seg = tid + 128 * i;              // 0..1023
        int row = seg >> 3, c16 = (seg & 7) << 4;   // byte offset within 128B row
        cp_async16(sstage + (unsigned)(row * 144 + c16),
                   Ap0 + (size_t)row * K + k0 + (c16 >> 1));
        cp_async16(sstage + (unsigned)(18432 + row * 144 + c16),
                   Bp0 + (size_t)row * K + k0 + (c16 >> 1));
    }
}

__device__ __forceinline__
void tgemm_body(const __half* __restrict__ A, const __half* __restrict__ B,
                float* __restrict__ C, int N, int K, float alpha, int mode)
{
    extern __shared__ float smem[];

    const int tid  = threadIdx.x;
    const int lane = tid & 31;
    const int wid  = tid >> 5;
    const int wm   = (wid & 1) * 64;
    const int wn   = (wid >> 1) * 64;
    const int r    = lane >> 2;
    const int c    = lane & 3;
    const int m0   = blockIdx.y * 128;
    const int n0   = blockIdx.x * 128;

    const unsigned sb = smem_u32(smem);
    const __half* Ap0 = A + (size_t)m0 * K;
    const __half* Bp0 = B + (size_t)n0 * K;

    float acc[4][8][4];
#pragma unroll
    for (int i = 0; i < 4; i++)
#pragma unroll
        for (int j = 0; j < 8; j++)
#pragma unroll
            for (int e = 0; e < 4; e++) acc[i][j][e] = 0.f;

    const int nit = K >> 6;               // 32
    tg_fill(sb, Ap0, Bp0, K, 0, tid);
    cp_commit();

    int cur = 0;
    for (int it = 0; it < nit; ++it) {
        if (it + 1 < nit) {
            int nstage = (it + 1) % 3;
            tg_fill(sb + (unsigned)nstage * STG_W * 4, Ap0, Bp0, K, (it + 1) << 6, tid);
        }
        cp_commit();
        asm volatile("cp.async.wait_group 1;");
        __syncthreads();

        const unsigned* As = (const unsigned*)smem + cur * STG_W;
        const unsigned* Bs = As + 4608;
#pragma unroll
        for (int ks = 0; ks < 4; ks++) {           // 4 k16 steps
            unsigned af[4][4], bf[8][2];
#pragma unroll
            for (int mi = 0; mi < 4; mi++) {
                const unsigned* ap = As + (wm + 16 * mi) * RPAD + 8 * ks + c;
                af[mi][0] = ap[r * RPAD];
                af[mi][1] = ap[(r + 8) * RPAD];
                af[mi][2] = ap[r * RPAD + 4];
                af[mi][3] = ap[(r + 8) * RPAD + 4];
            }
#pragma unroll
            for (int nj = 0; nj < 8; nj++) {
                const unsigned* bp = Bs + (wn + 8 * nj) * RPAD + 8 * ks + c;
                bf[nj][0] = bp[r * RPAD];
                bf[nj][1] = bp[r * RPAD + 4];
            }
#pragma unroll
            for (int mi = 0; mi < 4; mi++)
#pragma unroll
                for (int nj = 0; nj < 8; nj++)
                    mma_f16(acc[mi][nj], af[mi], bf[nj]);
        }
        cur = (cur == 2) ? 0 : cur + 1;
    }

    if (mode == 0) {
#pragma unroll
        for (int mi = 0; mi < 4; mi++)
#pragma unroll
            for (int nj = 0; nj < 8; nj++) {
                int row = m0 + wm + 16 * mi + r;
                int col = n0 + wn + 8 * nj + 2 * c;
                *(float2*)(C + (size_t)row * N + col) =
                    make_float2(alpha * acc[mi][nj][0], alpha * acc[mi][nj][1]);
                *(float2*)(C + (size_t)(row + 8) * N + col) =
                    make_float2(alpha * acc[mi][nj][2], alpha * acc[mi][nj][3]);
            }
        return;
    }
    if (mode == 1) {                       // V: fp16 store
#pragma unroll
        for (int mi = 0; mi < 4; mi++)
#pragma unroll
            for (int nj = 0; nj < 8; nj++) {
                int row = m0 + wm + 16 * mi + r;
                int col = n0 + wn + 8 * nj + 2 * c;
                *(unsigned*)(g_V + (size_t)row * N + col)       = h2pack(acc[mi][nj][0], acc[mi][nj][1]);
                *(unsigned*)(g_V + (size_t)(row + 8) * N + col) = h2pack(acc[mi][nj][2], acc[mi][nj][3]);
            }
        return;
    }

    // ---- fused rmsnorm + (head-indexed) rotary epilogue (Q/K GEMMs) ----
    __syncthreads();
    float* tile = smem;                 // 128 x 132 fp32
    float* cs   = smem + 16896;         // cj[64], sj[64]
#pragma unroll
    for (int mi = 0; mi < 4; mi++)
#pragma unroll
        for (int nj = 0; nj < 8; nj++) {
            int rr  = wm + 16 * mi + r;
            int cc2 = wn + 8 * nj + 2 * c;
            tile[rr * 132 + cc2]           = acc[mi][nj][0];
            tile[rr * 132 + cc2 + 1]       = acc[mi][nj][1];
            tile[(rr + 8) * 132 + cc2]     = acc[mi][nj][2];
            tile[(rr + 8) * 132 + cc2 + 1] = acc[mi][nj][3];
        }
    const int h    = n0 >> 8;
    const int half = (n0 >> 7) & 1;
    if (tid < 64) {
        // buggy-rotary angle: position index = head index h
        float ang = (float)h * exp2f(-(float)tid * (13.287712379549449f / 64.0f));
        cs[tid]      = cosf(ang);
        cs[64 + tid] = sinf(ang);
    }
    __syncthreads();

    {
        const int row = tid;
        const float* tr = tile + row * 132;
        float ss = 0.f;
#pragma unroll
        for (int i = 0; i < 32; i++) {
            float4 v4 = *(const float4*)(tr + 4 * i);
            ss += v4.x * v4.x + v4.y * v4.y + v4.z * v4.z + v4.w * v4.w;
        }
        const float osc = (mode == 2) ? (SCALE * 1.4426950408889634f) : 1.0f;
        const float rn  = rsqrtf(ss * (1.0f / 128.0f) + 1.1920929e-07f) * osc;

        const int bt = m0 + row;
        const int b  = bt >> 11;
        const int tt = bt & 2047;
        __half* dst = (mode == 2) ? (half ? g_q2 : g_q1) : (half ? g_k2 : g_k1);
        dst += ((size_t)(b * NH + h) * Tt + tt) * HH;

#pragma unroll
        for (int jb = 0; jb < 16; jb++) {
            float4 v4 = *(const float4*)(tr + 4 * jb);
            float4 p4 = *(const float4*)(tr + 64 + 4 * jb);
            float c0 = cs[4 * jb + 0], c1 = cs[4 * jb + 1];
            float c2 = cs[4 * jb + 2], c3 = cs[4 * jb + 3];
            float s0 = cs[64 + 4 * jb + 0], s1 = cs[64 + 4 * jb + 1];
            float s2 = cs[64 + 4 * jb + 2], s3 = cs[64 + 4 * jb + 3];
            uint2 lo, hi;
            lo.x = h2pack(rn * (v4.x * c0 + p4.x * s0), rn * (v4.y * c1 + p4.y * s1));
            lo.y = h2pack(rn * (v4.z * c2 + p4.z * s2), rn * (v4.w * c3 + p4.w * s3));
            hi.x = h2pack(rn * (p4.x * c0 - v4.x * s0), rn * (p4.y * c1 - v4.y * s1));
            hi.y = h2pack(rn * (p4.z * c2 - v4.z * s2), rn * (p4.w * c3 - v4.w * s3));
            *(uint2*)(dst + 4 * jb)      = lo;
            *(uint2*)(dst + 64 + 4 * jb) = hi;
        }
    }
}

__global__ __launch_bounds__(128, 2)
void tgemm_qkv()
{
    const __half* B = (blockIdx.z == 0) ? g_Wq : (blockIdx.z == 1) ? g_Wk : g_Wv;
    int mode = (blockIdx.z == 0) ? 2 : (blockIdx.z == 1) ? 3 : 1;
    tgemm_body(g_X, B, (float*)0, Cc, Cc, 1.0f, mode);
}

__global__ __launch_bounds__(128, 2)
void tgemm_wo(float* __restrict__ out)
{
    tgemm_body(g_y, g_Wo, out, Cc, Cc, 0.8f, 0);
}

// ---------------- fp16 tensor-core dual causal flash attention ----------------
// grid (16 bh, 32 qtiles reversed), 256 thr = 8 warps = 4 M-strips x 2 branches.
// 64-key tiles, double-buffered cp.async; V via ldmatrix.trans.
// R17: Q fragments hoisted into registers (loaded once at tile 0).
__global__ __launch_bounds__(256, 1)
void attn_tc()
{
    extern __shared__ float smf[];
    unsigned* k_s = (unsigned*)smf + 8704;  // K region (Q region only used for load + epilogue)

    const int tid   = threadIdx.x;
    const int lane  = tid & 31;
    const int w     = tid >> 5;
    const int g     = lane >> 2;
    const int t     = lane & 3;
    const int br    = w & 1;
    const int strip = w >> 1;
    const int mrow  = strip * 16;
    const int bh    = blockIdx.x;
    const int qt    = (int)gridDim.y - 1 - (int)blockIdx.y;  // big tiles first
    const int q0    = qt * 64;
    const int ntiles = qt + 1;

    const unsigned qsb = smem_u32(smf);
    const unsigned ksb = qsb + 8704u * 4;
    const unsigned vsb = qsb + 26112u * 4;

    const int b_ = bh >> 3, h_ = bh & 7;
    const __half* q1b = g_q1 + (size_t)bh * Tt * HH;
    const __half* q2b = g_q2 + (size_t)bh * Tt * HH;
    const __half* k1b = g_k1 + (size_t)bh * Tt * HH;
    const __half* k2b = g_k2 + (size_t)bh * Tt * HH;
    const __half* vsrc = g_V + (size_t)(b_ * Tt) * Cc + h_ * HD;

    // Q tile
    for (int i = tid; i < 2048; i += 256) {
        int bq = i >> 10;
        int r  = (i >> 4) & 63;
        int c16 = (i & 15) << 4;
        cp_async16(qsb + (unsigned)((bq * 4352 + r * 68) * 4 + c16),
                   q1b + (bq ? (q2b - q1b) : 0) + (size_t)(q0 + r) * HH + (c16 >> 1));
    }
    // K/V tile 0 into buffer 0
    for (int i = tid; i < 2048; i += 256) {
        int bq = i >> 10;
        int r  = (i >> 4) & 63;
        int c16 = (i & 15) << 4;
        cp_async16(ksb + (unsigned)((bq * 4352 + r * 68) * 4 + c16),
                   k1b + (bq ? (k2b - k1b) : 0) + (size_t)r * HH + (c16 >> 1));
    }
    for (int i = tid; i < 2048; i += 256) {
        int r  = i >> 5;
        int c16 = (i & 31) << 4;
        cp_async16(vsb + (unsigned)(r * 132 * 4 + c16), vsrc + (size_t)r * Cc + (c16 >> 1));
    }
    cp_commit();

    float oa[32][4];
#pragma unroll
    for (int i = 0; i < 32; i++) { oa[i][0]=0.f; oa[i][1]=0.f; oa[i][2]=0.f; oa[i][3]=0.f; }
    float m0 = -1e30f, m1 = -1e30f, l0 = 0.f, l1 = 0.f;
    unsigned qf[8][4];                    // hoisted Q fragments (loaded at kb==0)

    for (int kb = 0; kb < ntiles; kb++) {
        const int buf = kb & 1;
        if (kb + 1 < ntiles) {
            const int kr = (kb + 1) * 64;
            const unsigned ko = (unsigned)((buf ^ 1) * 8704) * 4;
            const unsigned vo = (unsigned)((buf ^ 1) * 8448) * 4;
            for (int i = tid; i < 2048; i += 256) {
                int bq = i >> 10;
                int r  = (i >> 4) & 63;
                int c16 = (i & 15) << 4;
                cp_async16(ksb + ko + (unsigned)((bq * 4352 + r * 68) * 4 + c16),
                           k1b + (bq ? (k2b - k1b) : 0) + (size_t)(kr + r) * HH + (c16 >> 1));
            }
            for (int i = tid; i < 2048; i += 256) {
                int r  = i >> 5;
                int c16 = (i & 31) << 4;
                cp_async16(vsb + vo + (unsigned)(r * 132 * 4 + c16),
                           vsrc + (size_t)(kr + r) * Cc + (c16 >> 1));
            }
        }
        cp_commit();
        asm volatile("cp.async.wait_group 1;");
        __syncthreads();

        if (kb == 0) {
            // one-time Q fragment load (Q invariant across key tiles)
            const unsigned* qb = (unsigned*)smf + br * 4352 + mrow * 68;
#pragma unroll
            for (int ks = 0; ks < 8; ks++) {
                int col = 8 * ks + t;
                qf[ks][0] = qb[g * 68 + col];
                qf[ks][1] = qb[(g + 8) * 68 + col];
                qf[ks][2] = qb[g * 68 + col + 4];
                qf[ks][3] = qb[(g + 8) * 68 + col + 4];
            }
        }

        // ---- S = Q K^T (16 rows x 64 keys, own branch), 8 k16 steps ----
        float sc[8][4];
#pragma unroll
        for (int nt = 0; nt < 8; nt++) { sc[nt][0]=0.f; sc[nt][1]=0.f; sc[nt][2]=0.f; sc[nt][3]=0.f; }
        {
            const unsigned* kk = k_s + buf * 8704 + br * 4352;
#pragma unroll
            for (int ks = 0; ks < 8; ks++) {
                int col = 8 * ks + t;
#pragma unroll
                for (int nt = 0; nt < 8; nt++) {
                    unsigned bb[2];
                    bb[0] = kk[(8 * nt + g) * 68 + col];
                    bb[1] = kk[(8 * nt + g) * 68 + col + 4];
                    mma_f16(sc[nt], qf[ks], bb);
                }
            }
        }

        // ---- causal mask (diagonal tile only) ----
        if (kb == qt) {
            int row0 = q0 + mrow + g;
            int row1 = row0 + 8;
#pragma unroll
            for (int nt = 0; nt < 8; nt++) {
                int kc = kb * 64 + 8 * nt + 2 * t;
                if (kc     > row0) sc[nt][0] = -1e30f;
                if (kc + 1 > row0) sc[nt][1] = -1e30f;
                if (kc     > row1) sc[nt][2] = -1e30f;
                if (kc + 1 > row1) sc[nt][3] = -1e30f;
            }
        }

        // ---- online softmax (base-2 domain), warp-local ----
        float mx0 = -1e30f, mx1 = -1e30f;
#pragma unroll
        for (int nt = 0; nt < 8; nt++) {
            mx0 = fmaxf(mx0, fmaxf(sc[nt][0], sc[nt][1]));
            mx1 = fmaxf(mx1, fmaxf(sc[nt][2], sc[nt][3]));
        }
        mx0 = fmaxf(mx0, __shfl_xor_sync(0xffffffffu, mx0, 1));
        mx0 = fmaxf(mx0, __shfl_xor_sync(0xffffffffu, mx0, 2));
        mx1 = fmaxf(mx1, __shfl_xor_sync(0xffffffffu, mx1, 1));
        mx1 = fmaxf(mx1, __shfl_xor_sync(0xffffffffu, mx1, 2));
        float nm0 = fmaxf(m0, mx0), nm1 = fmaxf(m1, mx1);
        float c0 = exp2f(m0 - nm0), c1 = exp2f(m1 - nm1);
        m0 = nm0; m1 = nm1;
        float s0 = 0.f, s1 = 0.f;
#pragma unroll
        for (int nt = 0; nt < 8; nt++) {
            sc[nt][0] = exp2f(sc[nt][0] - m0);
            sc[nt][1] = exp2f(sc[nt][1] - m0);
            sc[nt][2] = exp2f(sc[nt][2] - m1);
            sc[nt][3] = exp2f(sc[nt][3] - m1);
            s0 += sc[nt][0] + sc[nt][1];
            s1 += sc[nt][2] + sc[nt][3];
        }
        s0 += __shfl_xor_sync(0xffffffffu, s0, 1);
        s0 += __shfl_xor_sync(0xffffffffu, s0, 2);
        s1 += __shfl_xor_sync(0xffffffffu, s1, 1);
        s1 += __shfl_xor_sync(0xffffffffu, s1, 2);
        l0 = l0 * c0 + s0;
        l1 = l1 * c1 + s1;
        if (c0 != 1.f || c1 != 1.f) {
#pragma unroll
            for (int nt = 0; nt < 32; nt++) {
                oa[nt][0] *= c0; oa[nt][1] *= c0;
                oa[nt][2] *= c1; oa[nt][3] *= c1;
            }
        }

        // ---- O += P V : P packs straight from C-frags; V via ldmatrix.trans ----
#pragma unroll
        for (int kp = 0; kp < 4; kp++) {           // four k16 steps over 64 keys
            unsigned pa[4];
            pa[0] = h2pack(sc[2 * kp][0],     sc[2 * kp][1]);
            pa[1] = h2pack(sc[2 * kp][2],     sc[2 * kp][3]);
            pa[2] = h2pack(sc[2 * kp + 1][0], sc[2 * kp + 1][1]);
            pa[3] = h2pack(sc[2 * kp + 1][2], sc[2 * kp + 1][3]);
            unsigned vrow = vsb + (unsigned)(buf * 8448 + (16 * kp + (lane & 15)) * 132) * 4;
#pragma unroll
            for (int nt = 0; nt < 32; nt++) {
                unsigned vb[2];
                ldmx2t(vb[0], vb[1], vrow + nt * 16);
                mma_f16(oa[nt], pa, vb);
            }
        }
        __syncthreads();
    }

    // ---- combine branches: y = O1/l1 - lam * O2/l2 -> fp16 ----
    float* ex = smf;                       // reuse Q region
    float lam = g_lam;
    if (br == 0) {
        float r0 = 1.f / l0, r1 = 1.f / l1;
        float* eb = ex + strip * 4096;
#pragma unroll
        for (int nt = 0; nt < 32; nt++) {
            eb[(nt * 4 + 0) * 32 + lane] = oa[nt][0] * r0;
            eb[(nt * 4 + 1) * 32 + lane] = oa[nt][1] * r0;
            eb[(nt * 4 + 2) * 32 + lane] = oa[nt][2] * r1;
            eb[(nt * 4 + 3) * 32 + lane] = oa[nt][3] * r1;
        }
    }
    __syncthreads();
    if (br == 1) {
        float r0 = lam / l0, r1 = lam / l1;
        const float* eb = ex + strip * 4096;
        int row0 = q0 + mrow + g;
        __half* y0p = g_y + ((size_t)(b_ * Tt) + row0) * Cc + h_ * HD;
        __half* y1p = y0p + (size_t)8 * Cc;
#pragma unroll
        for (int nt = 0; nt < 32; nt++) {
            int col = 8 * nt + 2 * t;
            *(unsigned*)(y0p + col) = h2pack(eb[(nt * 4 + 0) * 32 + lane] - oa[nt][0] * r0,
                                             eb[(nt * 4 + 1) * 32 + lane] - oa[nt][1] * r0);
            *(unsigned*)(y1p + col) = h2pack(eb[(nt * 4 + 2) * 32 + lane] - oa[nt][2] * r1,
                                             eb[(nt * 4 + 3) * 32 + lane] - oa[nt][3] * r1);
        }
    }
}

// ---------------- launcher ----------------
extern "C" void kernel_launch(void* const* d_in, const int* in_sizes, int n_in,
                              void* d_out, int out_size)
{
    const float* x   = (const float*)d_in[0];
    const float* wq  = (const float*)d_in[1];
    const float* wk  = (const float*)d_in[2];
    const float* wv  = (const float*)d_in[3];
    const float* wo  = (const float*)d_in[4];
    const float* lq1 = (const float*)d_in[5];
    const float* lk1 = (const float*)d_in[6];
    const float* lq2 = (const float*)d_in[7];
    const float* lk2 = (const float*)d_in[8];
    float* out = (float*)d_out;

    cudaFuncSetAttribute(tgemm_qkv, cudaFuncAttributeMaxDynamicSharedMemorySize, GSM);
    cudaFuncSetAttribute(tgemm_wo,  cudaFuncAttributeMaxDynamicSharedMemorySize, GSM);

    cvt_kernel<<<dim3(4096, 1, 6), 256>>>(x, wq, wk, wv, wo, lq1, lk1, lq2, lk2);
    tgemm_qkv<<<dim3(Cc / 128, (Bsz * Tt) / 128, 3), 128, GSM>>>();

    int smem = 43008 * 4;   // 172032 B
    cudaFuncSetAttribute(attn_tc, cudaFuncAttributeMaxDynamicSharedMemorySize, smem);
    attn_tc<<<dim3(Bsz * NH, Tt / 64), 256, smem>>>();

    tgemm_wo<<<dim3(Cc / 128, (Bsz * Tt) / 128), 128, GSM>>>(out);
}